// round 12
// baseline (speedup 1.0000x reference)
#include <cuda_runtime.h>
#include <cstdint>

#define BB 64
#define HH 512
#define WW 512
#define NBOX 160
#define SLABS 32
#define SLAB_ROWS 16   // HH / SLABS
#define THREADS 128
#define NUNITS (BB * SLABS)   // 2048 work units, one per CTA
#define NTILES 16             // 16 column tiles of 32 cols each

// Per-unit partials: fully overwritten every launch (no zeroing needed).
__device__ float g_all[NUNITS];
__device__ float g_pnt[NUNITS];
__device__ int   g_cnt[NUNITS];
__device__ int   g_ticket = 0;

// bits [p, q), 0 <= p < q <= 16
__device__ __forceinline__ uint32_t rmask16(int p, int q) {
    int n = q - p;
    return ((0xFFFFu >> (16 - n)) << p) & 0xFFFFu;
}

__device__ __forceinline__ float sigmoidf(float x) {
    return __fdividef(1.f, 1.f + __expf(-x));
}

__global__ __launch_bounds__(THREADS, 10)
void motion_mask_fused(const float* __restrict__ pred,
                       const int*   __restrict__ tgt,
                       float*       __restrict__ out) {
    // Per-column-tile box lists: entry = (rowmask16, y1 | len<<16)
    __shared__ int   s_cnt[NTILES];
    __shared__ uint2 s_box[NTILES * NBOX];

    const int tid  = threadIdx.x;
    const int slab = blockIdx.x;               // 0..31
    const int b    = blockIdx.y;               // 0..63
    const int r0   = slab * SLAB_ROWS;
    const int lane = tid & 31, warp = tid >> 5;

    if (tid < NTILES) s_cnt[tid] = 0;
    __syncthreads();

    // ---- bin boxes into 32-col tiles (O(incidences)) ----
    for (int j = tid; j < NBOX; j += THREADS) {
        int4 t4 = ((const int4*)tgt)[b * NBOX + j];   // (x, y, sx, sy)
        int x1 = min(t4.x, HH);
        int x2 = min(t4.x + t4.z, HH);
        int y1 = min(t4.y, WW);
        int y2 = min(t4.y + t4.w, WW);
        int a = max(x1 - r0, 0);
        int e = min(x2 - r0, SLAB_ROWS);
        if (e > a && y2 > y1) {
            uint32_t rm   = rmask16(a, e);
            uint32_t pack = (uint32_t)y1 | ((uint32_t)(y2 - y1) << 16);
            int t1 = y1 >> 5, t2 = (y2 - 1) >> 5;
            for (int t = t1; t <= t2; t++) {
                int pos = atomicAdd(&s_cnt[t], 1);
                s_box[t * NBOX + pos] = make_uint2(rm, pack);
            }
        }
    }
    __syncthreads();

    // ---- thread layout: 128 threads x 4 columns x 16 rows ----
    const int c0   = tid * 4;
    const int tile = tid >> 3;

    uint32_t mm0 = 0, mm1 = 0, mm2 = 0, mm3 = 0;
    {
        const int n    = s_cnt[tile];
        const int base = tile * NBOX;
        for (int j = 0; j < n; j++) {
            uint2 e = s_box[base + j];
            uint32_t y1  = e.y & 0xFFFFu;
            uint32_t len = e.y >> 16;
            if ((uint32_t)(c0     - y1) < len) mm0 |= e.x;
            if ((uint32_t)(c0 + 1 - y1) < len) mm1 |= e.x;
            if ((uint32_t)(c0 + 2 - y1) < len) mm2 |= e.x;
            if ((uint32_t)(c0 + 3 - y1) < len) mm3 |= e.x;
        }
    }
    int cnt = __popc(mm0) + __popc(mm1) + __popc(mm2) + __popc(mm3);

    // ---- pixel loop: float4 loads, sigmoid, constant-bit predicated adds ----
    const float* base = pred + (size_t)b * HH * WW + (size_t)r0 * WW + c0;
    float s_all = 0.f, s_pnt = 0.f;
#pragma unroll
    for (int rr = 0; rr < SLAB_ROWS; rr++) {
        float4 v = *(const float4*)(base + (size_t)rr * WW);
        float sg0 = sigmoidf(v.x);
        float sg1 = sigmoidf(v.y);
        float sg2 = sigmoidf(v.z);
        float sg3 = sigmoidf(v.w);
        s_all += (sg0 + sg1) + (sg2 + sg3);
        const uint32_t bit = 1u << rr;         // compile-time constant per body
        if (mm0 & bit) s_pnt += sg0;
        if (mm1 & bit) s_pnt += sg1;
        if (mm2 & bit) s_pnt += sg2;
        if (mm3 & bit) s_pnt += sg3;
    }

    // ---- block reduction (4 warps) ----
#pragma unroll
    for (int o = 16; o; o >>= 1) {
        s_all += __shfl_down_sync(0xFFFFFFFFu, s_all, o);
        s_pnt += __shfl_down_sync(0xFFFFFFFFu, s_pnt, o);
        cnt   += __shfl_down_sync(0xFFFFFFFFu, cnt, o);
    }
    __shared__ float w_all[THREADS / 32], w_pnt[THREADS / 32];
    __shared__ int   w_cnt[THREADS / 32];
    if (lane == 0) { w_all[warp] = s_all; w_pnt[warp] = s_pnt; w_cnt[warp] = cnt; }
    __syncthreads();

    __shared__ bool s_isLast;
    if (tid == 0) {
        float ta = 0.f, tp = 0.f; int tc = 0;
#pragma unroll
        for (int i = 0; i < THREADS / 32; i++) { ta += w_all[i]; tp += w_pnt[i]; tc += w_cnt[i]; }
        const int u = b * SLABS + slab;
        g_all[u] = ta;
        g_pnt[u] = tp;
        g_cnt[u] = tc;
        __threadfence();
        int t = atomicAdd(&g_ticket, 1);
        s_isLast = (t == NUNITS - 1);
    }
    __syncthreads();

    // ---- last CTA finalizes (deterministic order, double precision) ----
    if (s_isLast) {
        __threadfence();  // acquire: make all units' stores visible
        __shared__ double s_loss[BB];
        if (tid < BB) {
            double S = 0.0, P = 0.0; long long C = 0;
#pragma unroll
            for (int i = 0; i < SLABS; i++) {
                int u = tid * SLABS + i;
                S += (double)g_all[u];
                P += (double)g_pnt[u];
                C += (long long)g_cnt[u];
            }
            double T = 255.0 * (double)C;   // target_sum
            double I = 255.0 * P;           // intersection
            s_loss[tid] = (I + 1.0) / (S + T - I + 1.0);
        }
        __syncthreads();
        if (tid == 0) {
            double acc = 0.0;
            for (int i = 0; i < BB; i++) acc += s_loss[i];
            out[0] = (float)(1.0 - acc / (double)BB);
            g_ticket = 0;   // reset for next graph replay
        }
    }
}

extern "C" void kernel_launch(void* const* d_in, const int* in_sizes, int n_in,
                              void* d_out, int out_size) {
    const float* pred = (const float*)d_in[0];   // pred_m  f32 (64,1,512,512)
    const int*   tgt  = (const int*)d_in[1];     // multi_targets i32 (64,5,32,4)
    float* out = (float*)d_out;

    dim3 grid(SLABS, BB);
    motion_mask_fused<<<grid, THREADS>>>(pred, tgt, out);
}

// round 13
// speedup vs baseline: 1.1618x; 1.1618x over previous
#include <cuda_runtime.h>
#include <cstdint>

#define BB 64
#define HH 512
#define WW 512
#define NBOX 160
#define SLABS 16
#define SLAB_ROWS 32   // HH / SLABS
#define THREADS 128
#define NUNITS (BB * SLABS)   // 1024 work units, one per CTA
#define NTILES 16             // 16 column tiles of 32 cols each

// Per-unit partials: fully overwritten every launch (no zeroing needed).
__device__ float g_all[NUNITS];
__device__ float g_pnt[NUNITS];
__device__ int   g_cnt[NUNITS];
__device__ int   g_ticket = 0;

// bits [p, q), 0 <= p < q <= 32
__device__ __forceinline__ uint32_t rmask32(int p, int q) {
    int n = q - p;
    return (0xFFFFFFFFu >> (32 - n)) << p;
}

__device__ __forceinline__ float sigmoidf(float x) {
    return __fdividef(1.f, 1.f + __expf(-x));
}

// 8 CTAs/SM cap -> 64 registers/thread: grid (1024) averages only 6.9 CTAs/SM,
// so this costs no occupancy while giving ptxas room to front-batch LDG.128s.
__global__ __launch_bounds__(THREADS, 8)
void motion_mask_fused(const float* __restrict__ pred,
                       const int*   __restrict__ tgt,
                       float*       __restrict__ out) {
    // Per-column-tile box lists: entry = (rowmask32, y1 | len<<16)
    __shared__ int   s_cnt[NTILES];
    __shared__ uint2 s_box[NTILES * NBOX];

    const int tid  = threadIdx.x;
    const int slab = blockIdx.x;               // 0..15
    const int b    = blockIdx.y;               // 0..63
    const int r0   = slab * SLAB_ROWS;
    const int lane = tid & 31, warp = tid >> 5;

    if (tid < NTILES) s_cnt[tid] = 0;
    __syncthreads();

    // ---- bin boxes into 32-col tiles (O(incidences)) ----
    for (int j = tid; j < NBOX; j += THREADS) {
        int4 t4 = ((const int4*)tgt)[b * NBOX + j];   // (x, y, sx, sy)
        int x1 = min(t4.x, HH);
        int x2 = min(t4.x + t4.z, HH);
        int y1 = min(t4.y, WW);
        int y2 = min(t4.y + t4.w, WW);
        int a = max(x1 - r0, 0);
        int e = min(x2 - r0, SLAB_ROWS);
        if (e > a && y2 > y1) {
            uint32_t rm   = rmask32(a, e);
            uint32_t pack = (uint32_t)y1 | ((uint32_t)(y2 - y1) << 16);
            int t1 = y1 >> 5, t2 = (y2 - 1) >> 5;
            for (int t = t1; t <= t2; t++) {
                int pos = atomicAdd(&s_cnt[t], 1);
                s_box[t * NBOX + pos] = make_uint2(rm, pack);
            }
        }
    }
    __syncthreads();

    // ---- thread layout: 128 threads x 4 columns x 32 rows ----
    const int c0   = tid * 4;
    const int tile = tid >> 3;

    uint32_t mm0 = 0, mm1 = 0, mm2 = 0, mm3 = 0;
    {
        const int n    = s_cnt[tile];
        const int base = tile * NBOX;
        for (int j = 0; j < n; j++) {
            uint2 e = s_box[base + j];
            uint32_t y1  = e.y & 0xFFFFu;
            uint32_t len = e.y >> 16;
            if ((uint32_t)(c0     - y1) < len) mm0 |= e.x;
            if ((uint32_t)(c0 + 1 - y1) < len) mm1 |= e.x;
            if ((uint32_t)(c0 + 2 - y1) < len) mm2 |= e.x;
            if ((uint32_t)(c0 + 3 - y1) < len) mm3 |= e.x;
        }
    }
    int cnt = __popc(mm0) + __popc(mm1) + __popc(mm2) + __popc(mm3);

    // ---- pixel loop: float4 loads, sigmoid, split accumulator chains ----
    const float* base = pred + (size_t)b * HH * WW + (size_t)r0 * WW + c0;
    float a0 = 0.f, a1 = 0.f, a2 = 0.f, a3 = 0.f;   // independent s_all chains
    float p0 = 0.f, p1 = 0.f;                        // independent s_pnt chains
#pragma unroll
    for (int rr = 0; rr < SLAB_ROWS; rr++) {
        float4 v = *(const float4*)(base + (size_t)rr * WW);
        float sg0 = sigmoidf(v.x);
        float sg1 = sigmoidf(v.y);
        float sg2 = sigmoidf(v.z);
        float sg3 = sigmoidf(v.w);
        a0 += sg0; a1 += sg1; a2 += sg2; a3 += sg3;
        const uint32_t bit = 1u << rr;         // compile-time constant per body
        if (mm0 & bit) p0 += sg0;
        if (mm1 & bit) p1 += sg1;
        if (mm2 & bit) p0 += sg2;
        if (mm3 & bit) p1 += sg3;
    }
    float s_all = (a0 + a1) + (a2 + a3);
    float s_pnt = p0 + p1;

    // ---- block reduction (4 warps) ----
#pragma unroll
    for (int o = 16; o; o >>= 1) {
        s_all += __shfl_down_sync(0xFFFFFFFFu, s_all, o);
        s_pnt += __shfl_down_sync(0xFFFFFFFFu, s_pnt, o);
        cnt   += __shfl_down_sync(0xFFFFFFFFu, cnt, o);
    }
    __shared__ float w_all[THREADS / 32], w_pnt[THREADS / 32];
    __shared__ int   w_cnt[THREADS / 32];
    if (lane == 0) { w_all[warp] = s_all; w_pnt[warp] = s_pnt; w_cnt[warp] = cnt; }
    __syncthreads();

    __shared__ bool s_isLast;
    if (tid == 0) {
        float ta = 0.f, tp = 0.f; int tc = 0;
#pragma unroll
        for (int i = 0; i < THREADS / 32; i++) { ta += w_all[i]; tp += w_pnt[i]; tc += w_cnt[i]; }
        const int u = b * SLABS + slab;
        g_all[u] = ta;
        g_pnt[u] = tp;
        g_cnt[u] = tc;
        __threadfence();
        int t = atomicAdd(&g_ticket, 1);
        s_isLast = (t == NUNITS - 1);
    }
    __syncthreads();

    // ---- last CTA finalizes (deterministic order, double precision) ----
    if (s_isLast) {
        __threadfence();  // acquire: make all units' stores visible
        __shared__ double s_loss[BB];
        if (tid < BB) {
            double S = 0.0, P = 0.0; long long C = 0;
#pragma unroll
            for (int i = 0; i < SLABS; i++) {
                int u = tid * SLABS + i;
                S += (double)g_all[u];
                P += (double)g_pnt[u];
                C += (long long)g_cnt[u];
            }
            double T = 255.0 * (double)C;   // target_sum
            double I = 255.0 * P;           // intersection
            s_loss[tid] = (I + 1.0) / (S + T - I + 1.0);
        }
        __syncthreads();
        if (tid == 0) {
            double acc = 0.0;
            for (int i = 0; i < BB; i++) acc += s_loss[i];
            out[0] = (float)(1.0 - acc / (double)BB);
            g_ticket = 0;   // reset for next graph replay
        }
    }
}

extern "C" void kernel_launch(void* const* d_in, const int* in_sizes, int n_in,
                              void* d_out, int out_size) {
    const float* pred = (const float*)d_in[0];   // pred_m  f32 (64,1,512,512)
    const int*   tgt  = (const int*)d_in[1];     // multi_targets i32 (64,5,32,4)
    float* out = (float*)d_out;

    dim3 grid(SLABS, BB);
    motion_mask_fused<<<grid, THREADS>>>(pred, tgt, out);
}

// round 15
// speedup vs baseline: 1.3924x; 1.1985x over previous
#include <cuda_runtime.h>
#include <cstdint>

#define BB 64
#define HH 512
#define WW 512
#define NBOX 160
#define SLABS 16
#define SLAB_ROWS 32   // HH / SLABS
#define THREADS 128
#define NUNITS (BB * SLABS)   // 1024 work units, one per CTA
#define NTILES 16             // 16 column tiles of 32 cols each
#define PF 4                  // software-pipeline prefetch depth

// Per-unit partials: fully overwritten every launch (no zeroing needed).
__device__ float g_all[NUNITS];
__device__ float g_pnt[NUNITS];
__device__ int   g_cnt[NUNITS];
__device__ int   g_ticket = 0;

// bits [p, q), 0 <= p < q <= 32
__device__ __forceinline__ uint32_t rmask32(int p, int q) {
    int n = q - p;
    return (0xFFFFFFFFu >> (32 - n)) << p;
}

__device__ __forceinline__ float sigmoidf(float x) {
    return __fdividef(1.f, 1.f + __expf(-x));
}

// Cap 7 CTAs/SM (grid avg is 6.92, so this costs no occupancy) -> 73 regs,
// giving ptxas room for the 4-deep rotating load buffer + batching.
__global__ __launch_bounds__(THREADS, 7)
void motion_mask_fused(const float* __restrict__ pred,
                       const int*   __restrict__ tgt,
                       float*       __restrict__ out) {
    // Per-column-tile box lists: entry = (rowmask32, y1 | len<<16)
    __shared__ int   s_cnt[NTILES];
    __shared__ uint2 s_box[NTILES * NBOX];

    const int tid  = threadIdx.x;
    const int slab = blockIdx.x;               // 0..15
    const int b    = blockIdx.y;               // 0..63
    const int r0   = slab * SLAB_ROWS;
    const int lane = tid & 31, warp = tid >> 5;

    if (tid < NTILES) s_cnt[tid] = 0;
    __syncthreads();

    // ---- bin boxes into 32-col tiles (O(incidences)) ----
    for (int j = tid; j < NBOX; j += THREADS) {
        int4 t4 = ((const int4*)tgt)[b * NBOX + j];   // (x, y, sx, sy)
        int x1 = min(t4.x, HH);
        int x2 = min(t4.x + t4.z, HH);
        int y1 = min(t4.y, WW);
        int y2 = min(t4.y + t4.w, WW);
        int a = max(x1 - r0, 0);
        int e = min(x2 - r0, SLAB_ROWS);
        if (e > a && y2 > y1) {
            uint32_t rm   = rmask32(a, e);
            uint32_t pack = (uint32_t)y1 | ((uint32_t)(y2 - y1) << 16);
            int t1 = y1 >> 5, t2 = (y2 - 1) >> 5;
            for (int t = t1; t <= t2; t++) {
                int pos = atomicAdd(&s_cnt[t], 1);
                s_box[t * NBOX + pos] = make_uint2(rm, pack);
            }
        }
    }
    __syncthreads();

    // ---- thread layout: 128 threads x 4 columns x 32 rows ----
    const int c0   = tid * 4;
    const int tile = tid >> 3;

    uint32_t mm0 = 0, mm1 = 0, mm2 = 0, mm3 = 0;
    {
        const int n    = s_cnt[tile];
        const int base = tile * NBOX;
        for (int j = 0; j < n; j++) {
            uint2 e = s_box[base + j];
            uint32_t y1  = e.y & 0xFFFFu;
            uint32_t len = e.y >> 16;
            if ((uint32_t)(c0     - y1) < len) mm0 |= e.x;
            if ((uint32_t)(c0 + 1 - y1) < len) mm1 |= e.x;
            if ((uint32_t)(c0 + 2 - y1) < len) mm2 |= e.x;
            if ((uint32_t)(c0 + 3 - y1) < len) mm3 |= e.x;
        }
    }
    int cnt = __popc(mm0) + __popc(mm1) + __popc(mm2) + __popc(mm3);

    // ---- pixel loop: 4-deep software pipeline, sigmoid, split accumulators ----
    const float* base = pred + (size_t)b * HH * WW + (size_t)r0 * WW + c0;

    float4 buf[PF];
#pragma unroll
    for (int i = 0; i < PF; i++)
        buf[i] = *(const float4*)(base + (size_t)i * WW);

    float a0 = 0.f, a1 = 0.f, a2 = 0.f, a3 = 0.f;   // independent s_all chains
    float p0 = 0.f, p1 = 0.f;                        // independent s_pnt chains
#pragma unroll
    for (int rr = 0; rr < SLAB_ROWS; rr++) {
        float4 v = buf[rr & (PF - 1)];
        if (rr + PF < SLAB_ROWS)
            buf[rr & (PF - 1)] = *(const float4*)(base + (size_t)(rr + PF) * WW);
        float sg0 = sigmoidf(v.x);
        float sg1 = sigmoidf(v.y);
        float sg2 = sigmoidf(v.z);
        float sg3 = sigmoidf(v.w);
        a0 += sg0; a1 += sg1; a2 += sg2; a3 += sg3;
        const uint32_t bit = 1u << rr;               // compile-time constant per body
        if (mm0 & bit) p0 += sg0;
        if (mm1 & bit) p1 += sg1;
        if (mm2 & bit) p0 += sg2;
        if (mm3 & bit) p1 += sg3;
    }
    float s_all = (a0 + a1) + (a2 + a3);
    float s_pnt = p0 + p1;

    // ---- block reduction (4 warps) ----
#pragma unroll
    for (int o = 16; o; o >>= 1) {
        s_all += __shfl_down_sync(0xFFFFFFFFu, s_all, o);
        s_pnt += __shfl_down_sync(0xFFFFFFFFu, s_pnt, o);
        cnt   += __shfl_down_sync(0xFFFFFFFFu, cnt, o);
    }
    __shared__ float w_all[THREADS / 32], w_pnt[THREADS / 32];
    __shared__ int   w_cnt[THREADS / 32];
    if (lane == 0) { w_all[warp] = s_all; w_pnt[warp] = s_pnt; w_cnt[warp] = cnt; }
    __syncthreads();

    __shared__ bool s_isLast;
    if (tid == 0) {
        float ta = 0.f, tp = 0.f; int tc = 0;
#pragma unroll
        for (int i = 0; i < THREADS / 32; i++) { ta += w_all[i]; tp += w_pnt[i]; tc += w_cnt[i]; }
        const int u = b * SLABS + slab;
        g_all[u] = ta;
        g_pnt[u] = tp;
        g_cnt[u] = tc;
        __threadfence();
        int t = atomicAdd(&g_ticket, 1);
        s_isLast = (t == NUNITS - 1);
    }
    __syncthreads();

    // ---- last CTA finalizes (parallel, deterministic, double precision) ----
    if (s_isLast) {
        __threadfence();  // acquire: make all units' stores visible
        double l = 0.0;
        if (tid < BB) {
            double S = 0.0, P = 0.0; long long C = 0;
#pragma unroll
            for (int i = 0; i < SLABS; i++) {
                int u = tid * SLABS + i;
                S += (double)g_all[u];
                P += (double)g_pnt[u];
                C += (long long)g_cnt[u];
            }
            double T = 255.0 * (double)C;   // target_sum
            double I = 255.0 * P;           // intersection
            l = (I + 1.0) / (S + T - I + 1.0);
        }
#pragma unroll
        for (int o = 16; o; o >>= 1) l += __shfl_down_sync(0xFFFFFFFFu, l, o);
        __shared__ double w_l[THREADS / 32];
        if (lane == 0) w_l[warp] = l;
        __syncthreads();
        if (tid == 0) {
            double acc = w_l[0] + w_l[1];   // warps 2,3 hold zero (tid >= 64)
            out[0] = (float)(1.0 - acc / (double)BB);
            g_ticket = 0;   // reset for next graph replay
        }
    }
}

extern "C" void kernel_launch(void* const* d_in, const int* in_sizes, int n_in,
                              void* d_out, int out_size) {
    const float* pred = (const float*)d_in[0];   // pred_m  f32 (64,1,512,512)
    const int*   tgt  = (const int*)d_in[1];     // multi_targets i32 (64,5,32,4)
    float* out = (float*)d_out;

    dim3 grid(SLABS, BB);
    motion_mask_fused<<<grid, THREADS>>>(pred, tgt, out);
}